// round 14
// baseline (speedup 1.0000x reference)
#include <cuda_runtime.h>

#define T_STEPS 128
#define BATCH   64
#define DFEAT   32
#define NSUP    1024
#define MROWS   8192
#define LSTM_BLOCKS 16
#define NBLOCKS (LSTM_BLOCKS + 256)   // 64 M-tiles x 4 blocks, each 2 N-subtiles

#define OUTS_OFF 0
#define RBF_OFF  32768
#define QK_OFF   (32768 + MROWS*NSUP)

#define LOG2E 1.4426950408889634f

typedef unsigned int u32;

__device__ __forceinline__ float tanh_hw(float z){
    float r;
    asm("tanh.approx.f32 %0, %1;" : "=f"(r) : "f"(z));
    return r;
}
__device__ __forceinline__ float sigm_hw(float z){
    return fmaf(0.5f, tanh_hw(0.5f*z), 0.5f);
}
__device__ __forceinline__ float ex2_hw(float z){
    float r;
    asm("ex2.approx.f32 %0, %1;" : "=f"(r) : "f"(z));
    return r;
}
__device__ __forceinline__ u32 tf32_rna(float x){
    u32 r;
    asm("cvt.rna.tf32.f32 %0, %1;" : "=r"(r) : "f"(x));
    return r;
}
__device__ __forceinline__ void tf32_split(float x, u32& hi, u32& lo){
    hi = tf32_rna(x);
    lo = tf32_rna(x - __uint_as_float(hi));
}
__device__ __forceinline__ void mma_tf32(float* d, const u32* a, u32 b0, u32 b1){
    asm volatile(
        "mma.sync.aligned.m16n8k8.row.col.f32.tf32.tf32.f32 "
        "{%0,%1,%2,%3}, {%4,%5,%6,%7}, {%8,%9}, {%0,%1,%2,%3};"
        : "+f"(d[0]), "+f"(d[1]), "+f"(d[2]), "+f"(d[3])
        : "r"(a[0]), "r"(a[1]), "r"(a[2]), "r"(a[3]), "r"(b0), "r"(b1));
}

__global__ __launch_bounds__(256, 2)
void hyb_kernel(const float* __restrict__ x,
                const float* __restrict__ sv,
                const float* __restrict__ Wf, const float* __restrict__ bf,
                const float* __restrict__ Wi, const float* __restrict__ bi,
                const float* __restrict__ Wu, const float* __restrict__ bu,
                const float* __restrict__ Wo, const float* __restrict__ bo,
                const float* __restrict__ pf, const float* __restrict__ pi,
                const float* __restrict__ pu, const float* __restrict__ po,
                const float* __restrict__ qkp,
                float* __restrict__ out)
{
    if (blockIdx.x < LSTM_BLOCKS) {
        // ================= LSTM role: one warp per batch element =================
        int warp = threadIdx.x >> 5;
        if (warp >= 4) return;
        int lane = threadIdx.x & 31;
        int b    = blockIdx.x * 4 + warp;
        int sl   = lane & 15;
        int g    = sl >> 2;
        int w    = sl & 3;

        const float* W  = (g==0)?Wf:(g==1)?Wi:(g==2)?Wu:Wo;
        const float* bb = (g==0)?bf:(g==1)?bi:(g==2)?bu:bo;
        const float* pp = (g==0)?pf:(g==1)?pi:(g==2)?pu:po;

        float wx[32];
        #pragma unroll
        for (int d=0; d<32; d++) wx[d] = W[w*36 + d];
        float wh0 = W[w*36+32], wh1 = W[w*36+33], wh2 = W[w*36+34], wh3 = W[w*36+35];
        float bias = bb[w] + pp[w];

        float h0=0.f,h1=0.f,h2=0.f,h3=0.f,cst=0.f;
        const unsigned FULL = 0xffffffffu;

        float dcur;
        {
            const float4* xp = (const float4*)(x + (size_t)b*DFEAT);
            float s0=bias, s1=0.f, s2=0.f, s3=0.f;
            #pragma unroll
            for (int q=0;q<8;q++){
                float4 v = xp[q];
                s0 = fmaf(wx[4*q+0], v.x, s0);
                s1 = fmaf(wx[4*q+1], v.y, s1);
                s2 = fmaf(wx[4*q+2], v.z, s2);
                s3 = fmaf(wx[4*q+3], v.w, s3);
            }
            dcur = (s0+s1)+(s2+s3);
        }

        for (int t=0; t<T_STEPS; t++){
            float theta = dcur;
            theta = fmaf(wh0,h0,theta);
            theta = fmaf(wh1,h1,theta);
            theta = fmaf(wh2,h2,theta);
            theta = fmaf(wh3,h3,theta);
            float cth = __cosf(theta);

            float dnext = bias;
            if (t < T_STEPS-1){
                const float4* xp = (const float4*)(x + ((size_t)(t+1)*BATCH + b)*DFEAT);
                float s0=bias, s1=0.f, s2=0.f, s3=0.f;
                #pragma unroll
                for (int q=0;q<8;q++){
                    float4 v = __ldg(&xp[q]);
                    s0 = fmaf(wx[4*q+0], v.x, s0);
                    s1 = fmaf(wx[4*q+1], v.y, s1);
                    s2 = fmaf(wx[4*q+2], v.z, s2);
                    s3 = fmaf(wx[4*q+3], v.w, s3);
                }
                dnext = (s0+s1)+(s2+s3);
            }

            int base = lane & ~3;
            float c0 = __shfl_sync(FULL, cth, base+0);
            float c1 = __shfl_sync(FULL, cth, base+1);
            float c2 = __shfl_sync(FULL, cth, base+2);
            float c3 = __shfl_sync(FULL, cth, base+3);
            float p01  = c0*c1;
            float p012 = p01*c2;
            float z = (w==0) ? c1*c2*c3 : (w==1) ? p01 : (w==2) ? p012 : p012*c3;
            float val = (g==2) ? tanh_hw(z) : sigm_hw(z);

            int hb = lane & 16;
            float fv = __shfl_sync(FULL, val, hb + 0  + w);
            float iv = __shfl_sync(FULL, val, hb + 4  + w);
            float uv = __shfl_sync(FULL, val, hb + 8  + w);
            float ov = __shfl_sync(FULL, val, hb + 12 + w);

            cst = fmaf(fv, cst, iv*uv);
            float ht = ov * tanh_hw(cst);
            if (lane < 4) out[OUTS_OFF + t*(BATCH*4) + b*4 + w] = ht;

            h0 = __shfl_sync(FULL, ht, base+0);
            h1 = __shfl_sync(FULL, ht, base+1);
            h2 = __shfl_sync(FULL, ht, base+2);
            h3 = __shfl_sync(FULL, ht, base+3);
            dcur = dnext;
        }
        return;
    }

    // ===== rbf + qk role: both GEMMs on tensor cores =====
    __shared__ __align__(16) float xs[32][132];      // k-major x tile
    __shared__ __align__(16) float ss[2][32][132];   // k-major s tiles
    __shared__ float xnorm[128];                     // ||x||^2 * log2e
    __shared__ float snorm[2][128];                  // ||s||^2 * log2e
    __shared__ float Fm[128][17];                    // 16-dim qk factors for x rows (pad 17)
    __shared__ float Gm[2][128][17];                 // 16-dim qk factors for s rows

    int bid2 = blockIdx.x - LSTM_BLOCKS;
    int mt = bid2 >> 2;
    int np = bid2 & 3;
    int m0 = mt * 128;
    int n0base = np * 256;
    int tid = threadIdx.x;
    int rbase = tid >> 3;
    int kc    = (tid & 7) * 4;

    // ---- single prologue: all gmem traffic up front ----
    {
        #pragma unroll
        for (int pass=0; pass<4; pass++){
            int r = rbase + pass*32;
            float4 v  = *(const float4*)(x  + (size_t)(m0 + r)*DFEAT + kc);
            float4 u0 = *(const float4*)(sv + (size_t)(n0base + r)*DFEAT + kc);
            float4 u1 = *(const float4*)(sv + (size_t)(n0base + 128 + r)*DFEAT + kc);
            xs[kc+0][r]=v.x;  xs[kc+1][r]=v.y;  xs[kc+2][r]=v.z;  xs[kc+3][r]=v.w;
            ss[0][kc+0][r]=u0.x; ss[0][kc+1][r]=u0.y; ss[0][kc+2][r]=u0.z; ss[0][kc+3][r]=u0.w;
            ss[1][kc+0][r]=u1.x; ss[1][kc+1][r]=u1.y; ss[1][kc+2][r]=u1.z; ss[1][kc+3][r]=u1.w;
        }
    }
    if (tid < 128){   // x row: norm + F factors
        const float4* xp = (const float4*)(x + (size_t)(m0 + tid)*DFEAT);
        float4 v0 = xp[0];
        float nrm = 0.f;
        #pragma unroll
        for (int q=0;q<8;q++){
            float4 v = xp[q];
            nrm = fmaf(v.x,v.x,nrm); nrm = fmaf(v.y,v.y,nrm);
            nrm = fmaf(v.z,v.z,nrm); nrm = fmaf(v.w,v.w,nrm);
        }
        xnorm[tid] = nrm * LOG2E;
        float fw[4] = {v0.x, v0.y, v0.z, v0.w};
        float c[4], s[4];
        #pragma unroll
        for (int w=0; w<4; w++){
            float th = fmaf(fw[w], 0.5f, qkp[w]*0.5f);
            __sincosf(th, &s[w], &c[w]);
        }
        float f01[4] = {c[0]*c[1], s[0]*c[1], c[0]*s[1], s[0]*s[1]};
        float f23[4] = {c[2]*c[3], s[2]*c[3], c[2]*s[3], s[2]*s[3]};
        #pragma unroll
        for (int i=0;i<16;i++) Fm[tid][i] = f01[i&3] * f23[i>>2];
    } else {          // s rows for BOTH subtiles: norm + G factors (sin negated)
        int r = tid - 128;
        #pragma unroll
        for (int sub=0; sub<2; sub++){
            const float4* sp = (const float4*)(sv + (size_t)(n0base + sub*128 + r)*DFEAT);
            float4 v0 = sp[0];
            float nrm = 0.f;
            #pragma unroll
            for (int q=0;q<8;q++){
                float4 v = sp[q];
                nrm = fmaf(v.x,v.x,nrm); nrm = fmaf(v.y,v.y,nrm);
                nrm = fmaf(v.z,v.z,nrm); nrm = fmaf(v.w,v.w,nrm);
            }
            snorm[sub][r] = nrm * LOG2E;
            float fw[4] = {v0.x, v0.y, v0.z, v0.w};
            float c[4], s[4];
            #pragma unroll
            for (int w=0; w<4; w++){
                float th = fmaf(fw[w], 0.5f, qkp[w]*0.5f);
                float ss_;
                __sincosf(th, &ss_, &c[w]);
                s[w] = -ss_;            // negated sin
            }
            float g01[4] = {c[0]*c[1], s[0]*c[1], c[0]*s[1], s[0]*s[1]};
            float g23[4] = {c[2]*c[3], s[2]*c[3], c[2]*s[3], s[2]*s[3]};
            #pragma unroll
            for (int i=0;i<16;i++) Gm[sub][r][i] = g01[i&3] * g23[i>>2];
        }
    }
    __syncthreads();   // the only barrier

    int lane = tid & 31;
    int wid  = tid >> 5;         // 0..7
    int m0w  = wid * 16;         // this warp's 16 M-rows within tile
    int ar   = lane >> 2;        // 0..7
    int ac   = lane & 3;         // 0..3
    float* rbf_out = out + RBF_OFF;
    float* qk_out  = out + QK_OFF;
    const float TL = 2.0f*LOG2E;

    #pragma unroll 1
    for (int sub = 0; sub < 2; sub++){
        int n0 = n0base + sub*128;
        const float (*ssb)[132] = ss[sub];
        const float (*gmb)[17]  = Gm[sub];
        const float* snb = snorm[sub];

        // ---- rbf GEMM: 16(M) x 128(N) x 32(K) per warp, 3xTF32 ----
        {
            float acc[16][4];
            #pragma unroll
            for (int nt=0; nt<16; nt++){
                acc[nt][0]=0.f; acc[nt][1]=0.f; acc[nt][2]=0.f; acc[nt][3]=0.f;
            }

            #pragma unroll
            for (int ks=0; ks<4; ks++){
                int k0 = ks*8;
                u32 ah[4], al[4];
                {
                    float a0f = xs[k0+ac  ][m0w+ar];
                    float a1f = xs[k0+ac  ][m0w+ar+8];
                    float a2f = xs[k0+ac+4][m0w+ar];
                    float a3f = xs[k0+ac+4][m0w+ar+8];
                    tf32_split(a0f, ah[0], al[0]);
                    tf32_split(a1f, ah[1], al[1]);
                    tf32_split(a2f, ah[2], al[2]);
                    tf32_split(a3f, ah[3], al[3]);
                }
                #pragma unroll
                for (int nt=0; nt<16; nt++){
                    float b0f = ssb[k0+ac  ][nt*8 + ar];
                    float b1f = ssb[k0+ac+4][nt*8 + ar];
                    u32 bh0, bl0, bh1, bl1;
                    tf32_split(b0f, bh0, bl0);
                    tf32_split(b1f, bh1, bl1);
                    mma_tf32(acc[nt], ah, bh0, bh1);
                    mma_tf32(acc[nt], ah, bl0, bl1);
                    mma_tf32(acc[nt], al, bh0, bh1);
                }
            }

            // rbf epilogue in mma C layout
            int r1 = m0w + ar;
            int r2 = r1 + 8;
            float xn1 = xnorm[r1];
            float xn2 = xnorm[r2];
            int cb = 2*ac;
            float* row1 = rbf_out + (size_t)(m0 + r1)*NSUP + n0;
            float* row2 = rbf_out + (size_t)(m0 + r2)*NSUP + n0;
            #pragma unroll
            for (int nt=0; nt<16; nt++){
                int c0 = nt*8 + cb;
                float sn0 = snb[c0];
                float sn1 = snb[c0+1];
                float2 o1, o2;
                o1.x = ex2_hw(fmaf(acc[nt][0], TL, -(xn1+sn0)));
                o1.y = ex2_hw(fmaf(acc[nt][1], TL, -(xn1+sn1)));
                o2.x = ex2_hw(fmaf(acc[nt][2], TL, -(xn2+sn0)));
                o2.y = ex2_hw(fmaf(acc[nt][3], TL, -(xn2+sn1)));
                *(float2*)(row1 + c0) = o1;
                *(float2*)(row2 + c0) = o2;
            }
        }

        // ---- qk GEMM: 16(M) x 128(N) x 16(K) per warp over F,G factors ----
        {
            float qac[16][4];
            #pragma unroll
            for (int nt=0; nt<16; nt++){
                qac[nt][0]=0.f; qac[nt][1]=0.f; qac[nt][2]=0.f; qac[nt][3]=0.f;
            }

            #pragma unroll
            for (int ks=0; ks<2; ks++){
                int k0 = ks*8;
                u32 ah[4], al[4];
                {
                    float a0f = Fm[m0w+ar  ][k0+ac];
                    float a1f = Fm[m0w+ar+8][k0+ac];
                    float a2f = Fm[m0w+ar  ][k0+ac+4];
                    float a3f = Fm[m0w+ar+8][k0+ac+4];
                    tf32_split(a0f, ah[0], al[0]);
                    tf32_split(a1f, ah[1], al[1]);
                    tf32_split(a2f, ah[2], al[2]);
                    tf32_split(a3f, ah[3], al[3]);
                }
                #pragma unroll
                for (int nt=0; nt<16; nt++){
                    float b0f = gmb[nt*8 + ar][k0+ac];
                    float b1f = gmb[nt*8 + ar][k0+ac+4];
                    u32 bh0, bl0, bh1, bl1;
                    tf32_split(b0f, bh0, bl0);
                    tf32_split(b1f, bh1, bl1);
                    mma_tf32(qac[nt], ah, bh0, bh1);
                    mma_tf32(qac[nt], ah, bl0, bl1);
                    mma_tf32(qac[nt], al, bh0, bh1);
                }
            }

            // qk epilogue: |acc| in mma C layout
            int r1 = m0w + ar;
            int r2 = r1 + 8;
            int cb = 2*ac;
            float* row1 = qk_out + (size_t)(m0 + r1)*NSUP + n0;
            float* row2 = qk_out + (size_t)(m0 + r2)*NSUP + n0;
            #pragma unroll
            for (int nt=0; nt<16; nt++){
                int c0 = nt*8 + cb;
                float2 o1, o2;
                o1.x = fabsf(qac[nt][0]);
                o1.y = fabsf(qac[nt][1]);
                o2.x = fabsf(qac[nt][2]);
                o2.y = fabsf(qac[nt][3]);
                *(float2*)(row1 + c0) = o1;
                *(float2*)(row2 + c0) = o2;
            }
        }
    }
}

extern "C" void kernel_launch(void* const* d_in, const int* in_sizes, int n_in,
                              void* d_out, int out_size)
{
    const float* x   = (const float*)d_in[0];
    const float* sv  = (const float*)d_in[1];
    const float* Wf  = (const float*)d_in[2];
    const float* bf  = (const float*)d_in[3];
    const float* Wi  = (const float*)d_in[4];
    const float* bi  = (const float*)d_in[5];
    const float* Wu  = (const float*)d_in[6];
    const float* bu  = (const float*)d_in[7];
    const float* Wo  = (const float*)d_in[8];
    const float* bo  = (const float*)d_in[9];
    const float* pf  = (const float*)d_in[10];
    const float* pi_ = (const float*)d_in[11];
    const float* pu  = (const float*)d_in[12];
    const float* po  = (const float*)d_in[13];
    const float* qkp = (const float*)d_in[14];

    hyb_kernel<<<NBLOCKS, 256>>>(x, sv, Wf, bf, Wi, bi, Wu, bu, Wo, bo,
                                 pf, pi_, pu, po, qkp, (float*)d_out);
}